// round 2
// baseline (speedup 1.0000x reference)
#include <cuda_runtime.h>
#include <cuda_bf16.h>

#define TT_  512
#define HH_  256
#define DD_  256

// Scratch: transposed gate weights, [dir][k][j] as float4 (i,f,g,o in xyzw)
__device__ float4 g_WihT4[2 * 256 * 256];   // 2 MB
__device__ float4 g_WhhT4[2 * 256 * 256];   // 2 MB

__device__ __forceinline__ float sigmf(float z) {
    return 1.0f / (1.0f + __expf(-z));
}

// ---------------------------------------------------------------------------
// Zero the output (harness poisons it to 0xAA; we accumulate with atomics).
// ---------------------------------------------------------------------------
__global__ void zero_out_kernel(float* __restrict__ out, int n) {
    int i = blockIdx.x * blockDim.x + threadIdx.x;
    int stride = gridDim.x * blockDim.x;
    for (; i < n; i += stride) out[i] = 0.0f;
}

// ---------------------------------------------------------------------------
// Prep: transpose Wih/Whh (4H, D) row-major -> [k][j] float4 over gates.
// g_WihT4[dir*65536 + k*256 + j] = (Wih[(0*256+j), k], Wih[(1*256+j), k], ...)
// ---------------------------------------------------------------------------
__global__ void prep_kernel(const float* __restrict__ Wih_fw,
                            const float* __restrict__ Whh_fw,
                            const float* __restrict__ Wih_bw,
                            const float* __restrict__ Whh_bw) {
    int i = blockIdx.x * blockDim.x + threadIdx.x;
    if (i >= 2 * 256 * 256) return;
    int dir = i >> 16;
    int rem = i & 65535;
    int k = rem >> 8;
    int j = rem & 255;
    const float* Wih = dir ? Wih_bw : Wih_fw;
    const float* Whh = dir ? Whh_bw : Whh_fw;
    g_WihT4[i] = make_float4(Wih[(0 * 256 + j) * 256 + k],
                             Wih[(1 * 256 + j) * 256 + k],
                             Wih[(2 * 256 + j) * 256 + k],
                             Wih[(3 * 256 + j) * 256 + k]);
    g_WhhT4[i] = make_float4(Whh[(0 * 256 + j) * 256 + k],
                             Whh[(1 * 256 + j) * 256 + k],
                             Whh[(2 * 256 + j) * 256 + k],
                             Whh[(3 * 256 + j) * 256 + k]);
}

// ---------------------------------------------------------------------------
// matvec for Q/R stages: out_j = sum_k v[k] * W[k*256 + j], two batch rows
// sharing each weight load.
// ---------------------------------------------------------------------------
__device__ __forceinline__ void matvec2(const float* __restrict__ W, int j,
                                        const float* __restrict__ v0,
                                        const float* __restrict__ v1,
                                        float& o0, float& o1) {
    float a0 = 0.0f, a1 = 0.0f;
#pragma unroll 4
    for (int k = 0; k < 256; k += 4) {
        float w0 = __ldg(W + (k + 0) * 256 + j);
        float w1 = __ldg(W + (k + 1) * 256 + j);
        float w2 = __ldg(W + (k + 2) * 256 + j);
        float w3 = __ldg(W + (k + 3) * 256 + j);
        float4 p0 = *(const float4*)(v0 + k);
        float4 p1 = *(const float4*)(v1 + k);
        a0 = fmaf(p0.x, w0, a0); a0 = fmaf(p0.y, w1, a0);
        a0 = fmaf(p0.z, w2, a0); a0 = fmaf(p0.w, w3, a0);
        a1 = fmaf(p1.x, w0, a1); a1 = fmaf(p1.y, w1, a1);
        a1 = fmaf(p1.z, w2, a1); a1 = fmaf(p1.w, w3, a1);
    }
    o0 = a0; o1 = a1;
}

// ---------------------------------------------------------------------------
// Main persistent kernel: 128 CTAs, each owns (dir, batch pair {2p, 2p+1}).
// 256 threads: thread j owns output unit j (and c[j]) of both rows.
// ---------------------------------------------------------------------------
__global__ void __launch_bounds__(256)
moglstm_main(const float* __restrict__ x,
             const int*   __restrict__ lengths,
             const float* __restrict__ Q,
             const float* __restrict__ R,
             const float* __restrict__ bih_fw, const float* __restrict__ bhh_fw,
             const float* __restrict__ bih_bw, const float* __restrict__ bhh_bw,
             float* __restrict__ out) {
    __shared__ __align__(16) float sx[2][256];   // current x (mogrified in place)
    __shared__ __align__(16) float shc[2][256];  // carried h
    __shared__ __align__(16) float shm[2][256];  // mogrified h (temp)

    const int j   = threadIdx.x;
    const int dir = blockIdx.x >> 6;
    const int pr  = blockIdx.x & 63;
    const int b0 = 2 * pr, b1 = 2 * pr + 1;
    const int len0 = lengths[b0];
    const int len1 = lengths[b1];
    const int lenmax = max(len0, len1);

    const float*  Qd  = Q + dir * 65536;
    const float*  Rd  = R + dir * 65536;
    const float4* WT4 = g_WihT4 + dir * 65536;
    const float4* UT4 = g_WhhT4 + dir * 65536;
    const float* bih = dir ? bih_bw : bih_fw;
    const float* bhh = dir ? bhh_bw : bhh_fw;

    const float bi = bih[j]       + bhh[j];
    const float bf = bih[256 + j] + bhh[256 + j];
    const float bg = bih[512 + j] + bhh[512 + j];
    const float bo = bih[768 + j] + bhh[768 + j];

    shc[0][j] = 0.0f;
    shc[1][j] = 0.0f;
    float c0 = 0.0f, c1 = 0.0f;

    const float* xb0 = x + (long long)b0 * TT_ * DD_;
    const float* xb1 = x + (long long)b1 * TT_ * DD_;

    for (int n = 0; n < lenmax; ++n) {
        const int tt = dir ? (lenmax - 1 - n) : n;
        const bool a0 = (tt < len0);
        const bool a1 = (tt < len1);

        __syncthreads();  // prev-iter smem reads done; shc writes visible

        // load x_t (thread j owns element j of each row)
        float xl0 = xb0[tt * DD_ + j];
        float xl1 = xb1[tt * DD_ + j];
        sx[0][j] = xl0;
        sx[1][j] = xl1;   // note: only self-consumed before stage-1 write

        // ---- stage 1: u = h @ Q ; x1 = 2*sig(u)*x ----
        float u0, u1;
        matvec2(Qd, j, shc[0], shc[1], u0, u1);
        sx[0][j] = 2.0f * sigmf(u0) * xl0;
        sx[1][j] = 2.0f * sigmf(u1) * xl1;
        __syncthreads();

        // ---- stage 2: v = x1 @ R ; h1 = 2*sig(v)*h ----
        float v0, v1;
        matvec2(Rd, j, sx[0], sx[1], v0, v1);
        shm[0][j] = 2.0f * sigmf(v0) * shc[0][j];
        shm[1][j] = 2.0f * sigmf(v1) * shc[1][j];
        __syncthreads();

        // ---- stage 3: u2 = h1 @ Q ; x2 = 2*sig(u2)*x1 ----
        matvec2(Qd, j, shm[0], shm[1], u0, u1);
        sx[0][j] = 2.0f * sigmf(u0) * sx[0][j];
        sx[1][j] = 2.0f * sigmf(u1) * sx[1][j];
        __syncthreads();

        // ---- stage 4: v2 = x2 @ R ; h2 = 2*sig(v2)*h1 ----
        matvec2(Rd, j, sx[0], sx[1], v0, v1);
        shm[0][j] = 2.0f * sigmf(v0) * shm[0][j];
        shm[1][j] = 2.0f * sigmf(v1) * shm[1][j];
        __syncthreads();

        // ---- stage 5: gates = x2 @ Wih^T + h2 @ Whh^T + b ----
        float gi0 = bi, gf0 = bf, gg0 = bg, go0 = bo;
        float gi1 = bi, gf1 = bf, gg1 = bg, go1 = bo;

#pragma unroll 2
        for (int k = 0; k < 256; k += 4) {
            float4 p0 = *(const float4*)&sx[0][k];
            float4 p1 = *(const float4*)&sx[1][k];
            float4 w;
            w = __ldg(WT4 + (k + 0) * 256 + j);
            gi0 = fmaf(p0.x, w.x, gi0); gf0 = fmaf(p0.x, w.y, gf0);
            gg0 = fmaf(p0.x, w.z, gg0); go0 = fmaf(p0.x, w.w, go0);
            gi1 = fmaf(p1.x, w.x, gi1); gf1 = fmaf(p1.x, w.y, gf1);
            gg1 = fmaf(p1.x, w.z, gg1); go1 = fmaf(p1.x, w.w, go1);
            w = __ldg(WT4 + (k + 1) * 256 + j);
            gi0 = fmaf(p0.y, w.x, gi0); gf0 = fmaf(p0.y, w.y, gf0);
            gg0 = fmaf(p0.y, w.z, gg0); go0 = fmaf(p0.y, w.w, go0);
            gi1 = fmaf(p1.y, w.x, gi1); gf1 = fmaf(p1.y, w.y, gf1);
            gg1 = fmaf(p1.y, w.z, gg1); go1 = fmaf(p1.y, w.w, go1);
            w = __ldg(WT4 + (k + 2) * 256 + j);
            gi0 = fmaf(p0.z, w.x, gi0); gf0 = fmaf(p0.z, w.y, gf0);
            gg0 = fmaf(p0.z, w.z, gg0); go0 = fmaf(p0.z, w.w, go0);
            gi1 = fmaf(p1.z, w.x, gi1); gf1 = fmaf(p1.z, w.y, gf1);
            gg1 = fmaf(p1.z, w.z, gg1); go1 = fmaf(p1.z, w.w, go1);
            w = __ldg(WT4 + (k + 3) * 256 + j);
            gi0 = fmaf(p0.w, w.x, gi0); gf0 = fmaf(p0.w, w.y, gf0);
            gg0 = fmaf(p0.w, w.z, gg0); go0 = fmaf(p0.w, w.w, go0);
            gi1 = fmaf(p1.w, w.x, gi1); gf1 = fmaf(p1.w, w.y, gf1);
            gg1 = fmaf(p1.w, w.z, gg1); go1 = fmaf(p1.w, w.w, go1);
        }
#pragma unroll 2
        for (int k = 0; k < 256; k += 4) {
            float4 p0 = *(const float4*)&shm[0][k];
            float4 p1 = *(const float4*)&shm[1][k];
            float4 w;
            w = __ldg(UT4 + (k + 0) * 256 + j);
            gi0 = fmaf(p0.x, w.x, gi0); gf0 = fmaf(p0.x, w.y, gf0);
            gg0 = fmaf(p0.x, w.z, gg0); go0 = fmaf(p0.x, w.w, go0);
            gi1 = fmaf(p1.x, w.x, gi1); gf1 = fmaf(p1.x, w.y, gf1);
            gg1 = fmaf(p1.x, w.z, gg1); go1 = fmaf(p1.x, w.w, go1);
            w = __ldg(UT4 + (k + 1) * 256 + j);
            gi0 = fmaf(p0.y, w.x, gi0); gf0 = fmaf(p0.y, w.y, gf0);
            gg0 = fmaf(p0.y, w.z, gg0); go0 = fmaf(p0.y, w.w, go0);
            gi1 = fmaf(p1.y, w.x, gi1); gf1 = fmaf(p1.y, w.y, gf1);
            gg1 = fmaf(p1.y, w.z, gg1); go1 = fmaf(p1.y, w.w, go1);
            w = __ldg(UT4 + (k + 2) * 256 + j);
            gi0 = fmaf(p0.z, w.x, gi0); gf0 = fmaf(p0.z, w.y, gf0);
            gg0 = fmaf(p0.z, w.z, gg0); go0 = fmaf(p0.z, w.w, go0);
            gi1 = fmaf(p1.z, w.x, gi1); gf1 = fmaf(p1.z, w.y, gf1);
            gg1 = fmaf(p1.z, w.z, gg1); go1 = fmaf(p1.z, w.w, go1);
            w = __ldg(UT4 + (k + 3) * 256 + j);
            gi0 = fmaf(p0.w, w.x, gi0); gf0 = fmaf(p0.w, w.y, gf0);
            gg0 = fmaf(p0.w, w.z, gg0); go0 = fmaf(p0.w, w.w, go0);
            gi1 = fmaf(p1.w, w.x, gi1); gf1 = fmaf(p1.w, w.y, gf1);
            gg1 = fmaf(p1.w, w.z, gg1); go1 = fmaf(p1.w, w.w, go1);
        }

        // ---- stage 6: elementwise LSTM + masked state commit + output ----
        {
            float ig = sigmf(gi0), fg = sigmf(gf0), og = sigmf(go0);
            float gg = tanhf(gg0);
            float cn = fg * c0 + ig * gg;
            float hn = og * tanhf(cn);
            if (a0) {
                c0 = cn;
                shc[0][j] = hn;
                atomicAdd(&out[((long long)b0 * TT_ + tt) * HH_ + j], hn);
            }
        }
        {
            float ig = sigmf(gi1), fg = sigmf(gf1), og = sigmf(go1);
            float gg = tanhf(gg1);
            float cn = fg * c1 + ig * gg;
            float hn = og * tanhf(cn);
            if (a1) {
                c1 = cn;
                shc[1][j] = hn;
                atomicAdd(&out[((long long)b1 * TT_ + tt) * HH_ + j], hn);
            }
        }
        // loop-top __syncthreads() protects sx/shm overwrite & shc visibility
    }
}

// ---------------------------------------------------------------------------
extern "C" void kernel_launch(void* const* d_in, const int* in_sizes, int n_in,
                              void* d_out, int out_size) {
    (void)in_sizes; (void)n_in;
    const float* x      = (const float*)d_in[0];
    const int*   lengths= (const int*)  d_in[1];
    const float* Q      = (const float*)d_in[2];
    const float* R      = (const float*)d_in[3];
    const float* Wih_fw = (const float*)d_in[4];
    const float* Whh_fw = (const float*)d_in[5];
    const float* bih_fw = (const float*)d_in[6];
    const float* bhh_fw = (const float*)d_in[7];
    const float* Wih_bw = (const float*)d_in[8];
    const float* Whh_bw = (const float*)d_in[9];
    const float* bih_bw = (const float*)d_in[10];
    const float* bhh_bw = (const float*)d_in[11];
    float* out = (float*)d_out;

    zero_out_kernel<<<2048, 256>>>(out, out_size);
    prep_kernel<<<512, 256>>>(Wih_fw, Whh_fw, Wih_bw, Whh_bw);
    moglstm_main<<<128, 256>>>(x, lengths, Q, R,
                               bih_fw, bhh_fw, bih_bw, bhh_bw, out);
}

// round 3
// speedup vs baseline: 3.0866x; 3.0866x over previous
#include <cuda_runtime.h>
#include <cuda_fp16.h>

#define TT_ 512
#define HH_ 256
#define DD_ 256

// Packed fp16 weights (prepared once per launch call):
// g_Qp/g_Rp: [dir][kc][j], kc = k/8, uint4 = 8 halves w[k..k+7][j]
// g_Wp/g_Up: [dir][kp][j], kp = k/2, uint4 = (i,f,g,o)@k , (i,f,g,o)@k+1
__device__ uint4 g_Qp[2 * 32 * 256];    // 256 KB
__device__ uint4 g_Rp[2 * 32 * 256];    // 256 KB
__device__ uint4 g_Wp[2 * 128 * 256];   // 1 MB
__device__ uint4 g_Up[2 * 128 * 256];   // 1 MB

static __device__ __forceinline__ unsigned packh2(float a, float b) {
    __half2 h = __halves2half2(__float2half_rn(a), __float2half_rn(b));
    return *reinterpret_cast<unsigned*>(&h);
}

// ---------------------------------------------------------------------------
// One kernel: zero the output AND pack weights to fp16.
// Grid is exactly out_size/4 threads (4,194,304 = 16384 x 256).
// ---------------------------------------------------------------------------
__global__ void prep_zero_kernel(const float* __restrict__ Q,
                                 const float* __restrict__ R,
                                 const float* __restrict__ Wih_fw,
                                 const float* __restrict__ Whh_fw,
                                 const float* __restrict__ Wih_bw,
                                 const float* __restrict__ Whh_bw,
                                 float4* __restrict__ out4, int n4) {
    int i = blockIdx.x * blockDim.x + threadIdx.x;
    if (i < n4) out4[i] = make_float4(0.f, 0.f, 0.f, 0.f);

    if (i < 16384) {                       // Qp
        int dir = i >> 13, rem = i & 8191, kc = rem >> 8, jj = rem & 255;
        const float* P = Q + dir * 65536;
        int k0 = kc * 8;
        uint4 r;
        r.x = packh2(P[(k0 + 0) * 256 + jj], P[(k0 + 1) * 256 + jj]);
        r.y = packh2(P[(k0 + 2) * 256 + jj], P[(k0 + 3) * 256 + jj]);
        r.z = packh2(P[(k0 + 4) * 256 + jj], P[(k0 + 5) * 256 + jj]);
        r.w = packh2(P[(k0 + 6) * 256 + jj], P[(k0 + 7) * 256 + jj]);
        g_Qp[i] = r;
    } else if (i < 32768) {                // Rp
        int m = i - 16384;
        int dir = m >> 13, rem = m & 8191, kc = rem >> 8, jj = rem & 255;
        const float* P = R + dir * 65536;
        int k0 = kc * 8;
        uint4 r;
        r.x = packh2(P[(k0 + 0) * 256 + jj], P[(k0 + 1) * 256 + jj]);
        r.y = packh2(P[(k0 + 2) * 256 + jj], P[(k0 + 3) * 256 + jj]);
        r.z = packh2(P[(k0 + 4) * 256 + jj], P[(k0 + 5) * 256 + jj]);
        r.w = packh2(P[(k0 + 6) * 256 + jj], P[(k0 + 7) * 256 + jj]);
        g_Rp[m] = r;
    } else if (i < 98304) {                // Wp (Wih)
        int m = i - 32768;
        int dir = m >> 15, rem = m & 32767, kp = rem >> 8, jj = rem & 255;
        const float* W = dir ? Wih_bw : Wih_fw;
        int k0 = 2 * kp;
        uint4 r;
        r.x = packh2(W[(0 * 256 + jj) * 256 + k0],     W[(1 * 256 + jj) * 256 + k0]);
        r.y = packh2(W[(2 * 256 + jj) * 256 + k0],     W[(3 * 256 + jj) * 256 + k0]);
        r.z = packh2(W[(0 * 256 + jj) * 256 + k0 + 1], W[(1 * 256 + jj) * 256 + k0 + 1]);
        r.w = packh2(W[(2 * 256 + jj) * 256 + k0 + 1], W[(3 * 256 + jj) * 256 + k0 + 1]);
        g_Wp[m] = r;
    } else if (i < 163840) {               // Up (Whh)
        int m = i - 98304;
        int dir = m >> 15, rem = m & 32767, kp = rem >> 8, jj = rem & 255;
        const float* W = dir ? Whh_bw : Whh_fw;
        int k0 = 2 * kp;
        uint4 r;
        r.x = packh2(W[(0 * 256 + jj) * 256 + k0],     W[(1 * 256 + jj) * 256 + k0]);
        r.y = packh2(W[(2 * 256 + jj) * 256 + k0],     W[(3 * 256 + jj) * 256 + k0]);
        r.z = packh2(W[(0 * 256 + jj) * 256 + k0 + 1], W[(1 * 256 + jj) * 256 + k0 + 1]);
        r.w = packh2(W[(2 * 256 + jj) * 256 + k0 + 1], W[(3 * 256 + jj) * 256 + k0 + 1]);
        g_Up[m] = r;
    }
}

// ---------------------------------------------------------------------------
__device__ __forceinline__ float sigmf(float z) {
    float e;
    asm("ex2.approx.f32 %0, %1;" : "=f"(e) : "f"(-1.442695041f * z));
    float r;
    asm("rcp.approx.f32 %0, %1;" : "=f"(r) : "f"(1.0f + e));
    return r;
}
__device__ __forceinline__ float tanha(float z) {
    return 2.0f * sigmf(2.0f * z) - 1.0f;   // abs err ~1e-6, safe
}

// 8 k-steps of the Q/R matvec for both batch rows (weights 8 halves in w).
__device__ __forceinline__ void accum8(uint4 w,
                                       const float* __restrict__ v0p,
                                       const float* __restrict__ v1p,
                                       float& a0, float& b0, float& a1, float& b1) {
    const __half2* wh = reinterpret_cast<const __half2*>(&w);
    float2 w01 = __half22float2(wh[0]);
    float2 w23 = __half22float2(wh[1]);
    float2 w45 = __half22float2(wh[2]);
    float2 w67 = __half22float2(wh[3]);
    float4 pA = *(const float4*)(v0p);
    float4 pB = *(const float4*)(v0p + 4);
    float4 qA = *(const float4*)(v1p);
    float4 qB = *(const float4*)(v1p + 4);
    a0 = fmaf(pA.x, w01.x, a0); b0 = fmaf(pA.y, w01.y, b0);
    a0 = fmaf(pA.z, w23.x, a0); b0 = fmaf(pA.w, w23.y, b0);
    a0 = fmaf(pB.x, w45.x, a0); b0 = fmaf(pB.y, w45.y, b0);
    a0 = fmaf(pB.z, w67.x, a0); b0 = fmaf(pB.w, w67.y, b0);
    a1 = fmaf(qA.x, w01.x, a1); b1 = fmaf(qA.y, w01.y, b1);
    a1 = fmaf(qA.z, w23.x, a1); b1 = fmaf(qA.w, w23.y, b1);
    a1 = fmaf(qB.x, w45.x, a1); b1 = fmaf(qB.y, w45.y, b1);
    a1 = fmaf(qB.z, w67.x, a1); b1 = fmaf(qB.w, w67.y, b1);
}

// matvec over 256 k for output column j, rows v0/v1. Loads batched 8-deep.
__device__ __forceinline__ void mv2(const uint4* __restrict__ Wp, int j,
                                    const float* __restrict__ v0,
                                    const float* __restrict__ v1,
                                    float& o0, float& o1) {
    float a0 = 0.f, b0 = 0.f, a1 = 0.f, b1 = 0.f;
    for (int g = 0; g < 4; ++g) {
        uint4 w[8];
#pragma unroll
        for (int t = 0; t < 8; ++t) w[t] = __ldg(Wp + (g * 8 + t) * 256 + j);
#pragma unroll
        for (int t = 0; t < 8; ++t)
            accum8(w[t], v0 + (g * 8 + t) * 8, v1 + (g * 8 + t) * 8, a0, b0, a1, b1);
    }
    o0 = a0 + b0;
    o1 = a1 + b1;
}

// gate accumulation for one k-pair (2 k's), both rows.
__device__ __forceinline__ void acc_gates(uint4 w, float x0, float x1,
                                          float y0, float y1,
                                          float& i0, float& f0, float& g0, float& o0,
                                          float& i1, float& f1, float& g1, float& o1) {
    const __half2* wh = reinterpret_cast<const __half2*>(&w);
    float2 ifa = __half22float2(wh[0]);   // (i,f) @ k
    float2 goa = __half22float2(wh[1]);   // (g,o) @ k
    float2 ifb = __half22float2(wh[2]);   // (i,f) @ k+1
    float2 gob = __half22float2(wh[3]);   // (g,o) @ k+1
    i0 = fmaf(x0, ifa.x, i0); f0 = fmaf(x0, ifa.y, f0);
    g0 = fmaf(x0, goa.x, g0); o0 = fmaf(x0, goa.y, o0);
    i0 = fmaf(x1, ifb.x, i0); f0 = fmaf(x1, ifb.y, f0);
    g0 = fmaf(x1, gob.x, g0); o0 = fmaf(x1, gob.y, o0);
    i1 = fmaf(y0, ifa.x, i1); f1 = fmaf(y0, ifa.y, f1);
    g1 = fmaf(y0, goa.x, g1); o1 = fmaf(y0, goa.y, o1);
    i1 = fmaf(y1, ifb.x, i1); f1 = fmaf(y1, ifb.y, f1);
    g1 = fmaf(y1, gob.x, g1); o1 = fmaf(y1, gob.y, o1);
}

// ---------------------------------------------------------------------------
// Main: 128 CTAs, each owns (dir, batch pair). 256 threads; thread j owns
// output unit j of both rows.
// ---------------------------------------------------------------------------
__global__ void __launch_bounds__(256, 1)
moglstm_main(const float* __restrict__ x,
             const int*   __restrict__ lengths,
             const float* __restrict__ bih_fw, const float* __restrict__ bhh_fw,
             const float* __restrict__ bih_bw, const float* __restrict__ bhh_bw,
             float* __restrict__ out) {
    __shared__ __align__(16) float sx[2][256];
    __shared__ __align__(16) float shm[2][256];
    __shared__ __align__(16) float shc[2][256];

    const int j   = threadIdx.x;
    const int dir = blockIdx.x >> 6;
    const int pr  = blockIdx.x & 63;
    const int b0 = 2 * pr, b1 = b0 + 1;
    const int len0 = lengths[b0];
    const int len1 = lengths[b1];
    const int lenmax = max(len0, len1);

    const uint4* Qp = g_Qp + dir * 8192;
    const uint4* Rp = g_Rp + dir * 8192;
    const uint4* Wp = g_Wp + dir * 32768;
    const uint4* Up = g_Up + dir * 32768;
    const float* bih = dir ? bih_bw : bih_fw;
    const float* bhh = dir ? bhh_bw : bhh_fw;
    const float bi = bih[j]       + bhh[j];
    const float bf = bih[256 + j] + bhh[256 + j];
    const float bg = bih[512 + j] + bhh[512 + j];
    const float bo = bih[768 + j] + bhh[768 + j];

    shc[0][j] = 0.f;
    shc[1][j] = 0.f;
    float c0 = 0.f, c1 = 0.f;

    const float* xb0 = x + (size_t)b0 * TT_ * DD_;
    const float* xb1 = x + (size_t)b1 * TT_ * DD_;

    for (int n = 0; n < lenmax; ++n) {
        const int tt = dir ? (lenmax - 1 - n) : n;
        const bool a0 = (tt < len0);
        const bool a1 = (tt < len1);

        __syncthreads();   // prior-iter smem reads done; shc commits visible

        float xl0 = __ldg(xb0 + tt * DD_ + j);
        float xl1 = __ldg(xb1 + tt * DD_ + j);

        // stage 1: u = h @ Q ; x1 = 2 sig(u) x
        float u0, u1;
        mv2(Qp, j, shc[0], shc[1], u0, u1);
        float x10 = 2.f * sigmf(u0) * xl0;
        float x11 = 2.f * sigmf(u1) * xl1;
        sx[0][j] = x10;
        sx[1][j] = x11;
        __syncthreads();

        // stage 2: v = x1 @ R ; h1 = 2 sig(v) h
        mv2(Rp, j, sx[0], sx[1], u0, u1);
        float h10 = 2.f * sigmf(u0) * shc[0][j];
        float h11 = 2.f * sigmf(u1) * shc[1][j];
        shm[0][j] = h10;
        shm[1][j] = h11;
        __syncthreads();

        // stage 3: u2 = h1 @ Q ; x2 = 2 sig(u2) x1
        mv2(Qp, j, shm[0], shm[1], u0, u1);
        sx[0][j] = 2.f * sigmf(u0) * x10;
        sx[1][j] = 2.f * sigmf(u1) * x11;
        __syncthreads();

        // stage 4: v2 = x2 @ R ; h2 = 2 sig(v2) h1
        mv2(Rp, j, sx[0], sx[1], u0, u1);
        shm[0][j] = 2.f * sigmf(u0) * h10;
        shm[1][j] = 2.f * sigmf(u1) * h11;
        __syncthreads();

        // stage 5: gates = x2 Wih^T + h2 Whh^T + b   (W and U interleaved)
        float gi0 = bi, gf0 = bf, gg0 = bg, go0 = bo;
        float gi1 = bi, gf1 = bf, gg1 = bg, go1 = bo;
#pragma unroll 2
        for (int kp = 0; kp < 128; kp += 2) {
            uint4 w0 = __ldg(Wp + (kp + 0) * 256 + j);
            uint4 w1 = __ldg(Wp + (kp + 1) * 256 + j);
            uint4 q0 = __ldg(Up + (kp + 0) * 256 + j);
            uint4 q1 = __ldg(Up + (kp + 1) * 256 + j);
            float4 xa = *(const float4*)&sx[0][kp * 2];
            float4 xb = *(const float4*)&sx[1][kp * 2];
            float4 ha = *(const float4*)&shm[0][kp * 2];
            float4 hb = *(const float4*)&shm[1][kp * 2];
            acc_gates(w0, xa.x, xa.y, xb.x, xb.y,
                      gi0, gf0, gg0, go0, gi1, gf1, gg1, go1);
            acc_gates(w1, xa.z, xa.w, xb.z, xb.w,
                      gi0, gf0, gg0, go0, gi1, gf1, gg1, go1);
            acc_gates(q0, ha.x, ha.y, hb.x, hb.y,
                      gi0, gf0, gg0, go0, gi1, gf1, gg1, go1);
            acc_gates(q1, ha.z, ha.w, hb.z, hb.w,
                      gi0, gf0, gg0, go0, gi1, gf1, gg1, go1);
        }

        // stage 6: elementwise LSTM + masked commit + accumulate output
        {
            float ig = sigmf(gi0), fg = sigmf(gf0), og = sigmf(go0);
            float gv = tanha(gg0);
            float cn = fg * c0 + ig * gv;
            float hn = og * tanha(cn);
            if (a0) {
                c0 = cn;
                shc[0][j] = hn;
                atomicAdd(&out[((size_t)b0 * TT_ + tt) * HH_ + j], hn);
            }
        }
        {
            float ig = sigmf(gi1), fg = sigmf(gf1), og = sigmf(go1);
            float gv = tanha(gg1);
            float cn = fg * c1 + ig * gv;
            float hn = og * tanha(cn);
            if (a1) {
                c1 = cn;
                shc[1][j] = hn;
                atomicAdd(&out[((size_t)b1 * TT_ + tt) * HH_ + j], hn);
            }
        }
    }
}

// ---------------------------------------------------------------------------
extern "C" void kernel_launch(void* const* d_in, const int* in_sizes, int n_in,
                              void* d_out, int out_size) {
    (void)in_sizes; (void)n_in;
    const float* x      = (const float*)d_in[0];
    const int*   lengths= (const int*)  d_in[1];
    const float* Q      = (const float*)d_in[2];
    const float* R      = (const float*)d_in[3];
    const float* Wih_fw = (const float*)d_in[4];
    const float* Whh_fw = (const float*)d_in[5];
    const float* bih_fw = (const float*)d_in[6];
    const float* bhh_fw = (const float*)d_in[7];
    const float* Wih_bw = (const float*)d_in[8];
    const float* Whh_bw = (const float*)d_in[9];
    const float* bih_bw = (const float*)d_in[10];
    const float* bhh_bw = (const float*)d_in[11];
    float* out = (float*)d_out;

    prep_zero_kernel<<<16384, 256>>>(Q, R, Wih_fw, Whh_fw, Wih_bw, Whh_bw,
                                     (float4*)out, out_size / 4);
    moglstm_main<<<128, 256>>>(x, lengths, bih_fw, bhh_fw, bih_bw, bhh_bw, out);
}